// round 6
// baseline (speedup 1.0000x reference)
#include <cuda_runtime.h>
#include <cstdint>

// Problem constants (fixed by setup_inputs)
#define NB 8
#define NH 100
#define NT 1000
#define NTS 80000   // NT * 80
#define BLK 256
#define SPAN 512       // samples per block (2 per thread)
#define NH2 (NH / 2)   // 50 harmonic pairs
#define NW 8           // interp columns per block window

// mod-2pi constants
#define INV2PI 0.15915494309189535f
#define MAGIC  12582912.0f                 // 1.5 * 2^23
// fusion-independent 3-term split of 2*pi (k < 2^18):
//   HI1 = 6.25 (5-bit sig: k*HI1 exact), HI2 = 17*2^-9 (exact), C3 = HI1+HI2-2pi
#define NHI1 (-6.25f)
#define NHI2 (-0.033203125f)
#define C3   (1.7817820414e-5f)

typedef unsigned long long u64;

// ---- packed f32x2 helpers (Blackwell sm_103a) ----
__device__ __forceinline__ u64 pk2(float lo, float hi) {
    u64 r; asm("mov.b64 %0, {%1, %2};" : "=l"(r) : "f"(lo), "f"(hi)); return r;
}
__device__ __forceinline__ void upk2(float& lo, float& hi, u64 v) {
    asm("mov.b64 {%0, %1}, %2;" : "=f"(lo), "=f"(hi) : "l"(v));
}
__device__ __forceinline__ u64 add2(u64 a, u64 b) {
    u64 r; asm("add.rn.f32x2 %0, %1, %2;" : "=l"(r) : "l"(a), "l"(b)); return r;
}
__device__ __forceinline__ u64 fma2(u64 a, u64 b, u64 c) {
    u64 r; asm("fma.rn.f32x2 %0, %1, %2, %3;" : "=l"(r) : "l"(a), "l"(b), "l"(c)); return r;
}

// smem entry: one LDS.128 = two aligned u64 lane-pairs
struct __align__(16) QPair { u64 x0; u64 d; };   // (x0_h, x0_h+1), (d_h, d_h+1)

// packed 2-harmonic sin with fusion-independent mod-2pi reduction
__device__ __forceinline__ u64 sin2_exact(
    u64 X2, u64 INV2, u64 MG2, u64 NMG2, u64 NH1_2, u64 NH2_2, u64 C3_2)
{
    u64 kb2 = fma2(X2, INV2, MG2);
    u64 kf2 = add2(kb2, NMG2);
    u64 d1  = fma2(kf2, NH1_2, X2);   // exact (k*6.25 exact product)
    u64 d2  = fma2(kf2, NH2_2, d1);   // exact
    u64 r2  = fma2(kf2, C3_2, d2);    // ~2e-7 err fused or split
    float r0, r1; upk2(r0, r1, r2);
    return pk2(__sinf(r0), __sinf(r1));
}

__global__ __launch_bounds__(BLK)
void HarmonicOscillator_kernel(
    const float* __restrict__ f0,   // [B,1,T]
    const float* __restrict__ hd,   // [B,H,T]
    const float* __restrict__ ps,   // [B,1,T]
    float* __restrict__ out)        // [B,Ts]
{
    __shared__ QPair q[NH2 * NW];

    const int s0 = blockIdx.x * SPAN;
    const int b  = blockIdx.y;

    const float R = (float)(999.0 / 79999.0);   // (T-1)/(Ts-1) rounded like jax f32

    // Block-uniform window start (i0 monotone; spans <= 7 values over 512 samples)
    int j0 = (int)__fmul_rn((float)s0, R);
    if (j0 > NT - 2) j0 = NT - 2;

    // --- cooperative smem fill: NH2*NW pair-entries ---
    {
        const float* hb = hd + (size_t)b * (NH * NT);
        for (int idx = threadIdx.x; idx < NH2 * NW; idx += BLK) {
            int h2 = idx >> 3;           // idx / 8
            int j  = idx & 7;
            int g0 = j0 + j;  if (g0 > NT - 1) g0 = NT - 1;
            int g1 = g0 + 1;  if (g1 > NT - 1) g1 = NT - 1;
            const float* r0 = hb + (2 * h2) * NT;
            const float* r1 = r0 + NT;
            float a0 = __ldg(r0 + g0), a1 = __ldg(r0 + g1);
            float b0 = __ldg(r1 + g0), b1 = __ldg(r1 + g1);
            q[idx].x0 = pk2(a0, b0);
            q[idx].d  = pk2(__fsub_rn(a1, a0), __fsub_rn(b1, b0));
        }
    }
    __syncthreads();

    // two samples per thread
    int sa = s0 + threadIdx.x;
    int sb = sa + BLK;
    bool va_ok = (sa < NTS);
    bool vb_ok = (sb < NTS);
    int sac = va_ok ? sa : (NTS - 1);
    int sbc = vb_ok ? sb : (NTS - 1);

    const float* f0b = f0 + b * NT;
    const float* psb = ps + b * NT;
    const float C = (float)(2.0 * 3.14159265358979323846 / 16000.0);

    // ---- per-sample setup (exact jnp f32 rounding) ----
    float sFa = (float)sac;
    float posa = __fmul_rn(sFa, R);
    int i0a = (int)posa; if (i0a > NT - 2) i0a = NT - 2;
    float wa = __fsub_rn(posa, (float)i0a);
    int lia = i0a - j0;

    float sFb = (float)sbc;
    float posb = __fmul_rn(sFb, R);
    int i0b = (int)posb; if (i0b > NT - 2) i0b = NT - 2;
    float wb = __fsub_rn(posb, (float)i0b);
    int lib = i0b - j0;

    float faa = __ldg(f0b + i0a), fab = __ldg(f0b + i0a + 1);
    float f0ua = __fadd_rn(faa, __fmul_rn(__fsub_rn(fab, faa), wa));
    float paa = __ldg(psb + i0a), pab = __ldg(psb + i0a + 1);
    float psua = __fadd_rn(paa, __fmul_rn(__fsub_rn(pab, paa), wa));
    float basea = __fmul_rn(__fmul_rn(C, f0ua), sFa);

    float fba = __ldg(f0b + i0b), fbb = __ldg(f0b + i0b + 1);
    float f0ub = __fadd_rn(fba, __fmul_rn(__fsub_rn(fbb, fba), wb));
    float pba = __ldg(psb + i0b), pbb = __ldg(psb + i0b + 1);
    float psub = __fadd_rn(pba, __fmul_rn(__fsub_rn(pbb, pba), wb));
    float baseb = __fmul_rn(__fmul_rn(C, f0ub), sFb);

    const QPair* qa = q + lia;
    const QPair* qb = q + lib;

    // packed loop-invariant operands
    u64 psua2 = pk2(psua, psua);
    u64 psub2 = pk2(psub, psub);
    u64 wa2   = pk2(wa, wa);
    u64 wb2   = pk2(wb, wb);
    u64 INV2  = pk2(INV2PI, INV2PI);
    u64 MG2   = pk2(MAGIC, MAGIC);
    u64 NMG2  = pk2(-MAGIC, -MAGIC);
    u64 NH1_2 = pk2(NHI1, NHI1);
    u64 NH2_2 = pk2(NHI2, NHI2);
    u64 C3_2  = pk2(C3, C3);

    u64 acca = pk2(0.0f, 0.0f);
    u64 accb = pk2(0.0f, 0.0f);

    float hOdd = 1.0f, hEven = 2.0f;   // exact integer recurrences

    #pragma unroll 10
    for (int h2 = 0; h2 < NH2; ++h2) {
        QPair va = qa[h2 * NW];                // LDS.128
        QPair vb = qb[h2 * NW];                // LDS.128

        // sample A: X = fl(fl(base*h) + psu), bit-exact vs reference
        float pa0 = __fmul_rn(basea, hOdd);
        float pa1 = __fmul_rn(basea, hEven);
        u64 Xa = add2(pk2(pa0, pa1), psua2);
        u64 s2a = sin2_exact(Xa, INV2, MG2, NMG2, NH1_2, NH2_2, C3_2);
        acca = fma2(s2a, fma2(va.d, wa2, va.x0), acca);

        // sample B (independent chain)
        float pb0 = __fmul_rn(baseb, hOdd);
        float pb1 = __fmul_rn(baseb, hEven);
        u64 Xb = add2(pk2(pb0, pb1), psub2);
        u64 s2b = sin2_exact(Xb, INV2, MG2, NMG2, NH1_2, NH2_2, C3_2);
        accb = fma2(s2b, fma2(vb.d, wb2, vb.x0), accb);

        hOdd  = __fadd_rn(hOdd, 2.0f);
        hEven = __fadd_rn(hEven, 2.0f);
    }

    float a0, a1; upk2(a0, a1, acca);
    float b0, b1; upk2(b0, b1, accb);
    float* outb = out + (size_t)b * NTS;
    if (va_ok) outb[sa] = __fadd_rn(a0, a1);
    if (vb_ok) outb[sb] = __fadd_rn(b0, b1);
}

extern "C" void kernel_launch(void* const* d_in, const int* in_sizes, int n_in,
                              void* d_out, int out_size) {
    const float* f0 = (const float*)d_in[0];
    const float* hd = (const float*)d_in[1];
    const float* ps = (const float*)d_in[2];
    float* out = (float*)d_out;

    dim3 block(BLK);
    dim3 grid((NTS + SPAN - 1) / SPAN, NB);
    HarmonicOscillator_kernel<<<grid, block>>>(f0, hd, ps, out);
}